// round 4
// baseline (speedup 1.0000x reference)
#include <cuda_runtime.h>
#include <math.h>

#define MAXN 1025
#define BATCH 8
#define C 128
#define NH 8
#define HD 16
#define L 4
#define TKA 128

typedef unsigned long long ull;

// ---------------- packed fp32x2 helpers (sm_103a FFMA2 path) ---------------
__device__ __forceinline__ ull pack2(float lo, float hi) {
    ull r; asm("mov.b64 %0, {%1, %2};" : "=l"(r) : "f"(lo), "f"(hi)); return r;
}
__device__ __forceinline__ float2 unpack2(ull v) {
    float lo, hi; asm("mov.b64 {%0, %1}, %2;" : "=f"(lo), "=f"(hi) : "l"(v));
    return make_float2(lo, hi);
}
__device__ __forceinline__ ull fma2(ull a, ull b, ull c) {
    ull d; asm("fma.rn.f32x2 %0, %1, %2, %3;" : "=l"(d) : "l"(a), "l"(b), "l"(c));
    return d;
}
__device__ __forceinline__ ull mul2(ull a, ull b) {
    ull d; asm("mul.rn.f32x2 %0, %1, %2;" : "=l"(d) : "l"(a), "l"(b));
    return d;
}
__device__ __forceinline__ ull add2(ull a, ull b) {
    ull d; asm("add.rn.f32x2 %0, %1, %2;" : "=l"(d) : "l"(a), "l"(b));
    return d;
}

// ---------------- device scratch (static, allocation-free) ----------------
__device__ float g_X0[BATCH*MAXN*C];
__device__ float g_X1[BATCH*MAXN*C];
__device__ float g_Q [BATCH*NH*MAXN*HD];
__device__ float g_K [BATCH*NH*MAXN*HD];
__device__ float g_V [BATCH*NH*MAXN*HD];
__device__ float g_O [BATCH*MAXN*C];
__device__ float g_H [BATCH*MAXN*512];
__device__ float g_CLSP[BATCH*NH*MAXN];
__device__ float g_WT[768*128];
__device__ int   g_order[BATCH][1024];
__device__ int   g_count[BATCH];
__device__ int   g_mk[3];
__device__ int   g_N;

// transpose conv_w (128,768) -> (768,128); also does global init
__global__ void k_transpose(const float* __restrict__ w) {
    int k = blockIdx.x, c = threadIdx.x;
    g_WT[k*128 + c] = w[c*768 + k];
    if (k == 0 && c == 0) {
        g_N = MAXN;
        g_mk[0] = 0; g_mk[1] = 0; g_mk[2] = 0;
    }
}

// ---------------- patch embed + cls row ------------------------------------
__global__ void __launch_bounds__(128) k_patch(
        const float* __restrict__ x, const float* __restrict__ cb,
        const float* __restrict__ cls, const float* __restrict__ pos,
        float* __restrict__ X) {
    int b = blockIdx.y;
    int tid = threadIdx.x;
    if (blockIdx.x == 64) {
        X[(size_t)b*MAXN*C + tid] = cls[tid] + pos[tid];
        return;
    }
    int t0 = blockIdx.x * 16;
    __shared__ __align__(16) float sPT[768][16];
    for (int v = tid; v < 768*16; v += 128) {
        int p = v & 15, k = v >> 4;
        int t = t0 + p;
        int ph = t >> 5, pw = t & 31;
        int ch = k >> 8, rem = k & 255, py = rem >> 4, px = rem & 15;
        sPT[k][p] = x[((size_t)(b*3 + ch)*512 + ph*16 + py)*512 + pw*16 + px];
    }
    __syncthreads();
    float bias = cb[tid];
    ull acc2[8];
    ull bini = pack2(bias, bias);
    #pragma unroll
    for (int j = 0; j < 8; j++) acc2[j] = bini;
    #pragma unroll 4
    for (int k = 0; k < 768; k++) {
        float w = g_WT[k*128 + tid];
        ull w2 = pack2(w, w);
        const ulonglong2* yr = (const ulonglong2*)&sPT[k][0];
        ulonglong2 y0 = yr[0], y1 = yr[1], y2 = yr[2], y3 = yr[3];
        acc2[0] = fma2(w2, y0.x, acc2[0]); acc2[1] = fma2(w2, y0.y, acc2[1]);
        acc2[2] = fma2(w2, y1.x, acc2[2]); acc2[3] = fma2(w2, y1.y, acc2[3]);
        acc2[4] = fma2(w2, y2.x, acc2[4]); acc2[5] = fma2(w2, y2.y, acc2[5]);
        acc2[6] = fma2(w2, y3.x, acc2[6]); acc2[7] = fma2(w2, y3.y, acc2[7]);
    }
    #pragma unroll
    for (int j = 0; j < 8; j++) {
        float2 u = unpack2(acc2[j]);
        int t = t0 + 2*j;
        X[((size_t)b*MAXN + 1 + t)*C + tid]     = u.x + pos[(1 + t)*C + tid];
        X[((size_t)b*MAXN + 2 + t)*C + tid]     = u.y + pos[(2 + t)*C + tid];
    }
}

// ---------------- LN helper (16 tokens, 128 threads) -----------------------
#define LN16_BODY(lwp, lbp)                                                     \
    {                                                                           \
        _Pragma("unroll")                                                       \
        for (int p = 0; p < 16; p++) {                                          \
            float s = xv[p];                                                    \
            _Pragma("unroll")                                                   \
            for (int o = 16; o; o >>= 1) s += __shfl_xor_sync(~0u, s, o);       \
            if (!lane) sRed[0][wid][p] = s;                                     \
        }                                                                       \
        __syncthreads();                                                        \
        _Pragma("unroll")                                                       \
        for (int p = 0; p < 16; p++) {                                          \
            float mu = (sRed[0][0][p] + sRed[0][1][p] + sRed[0][2][p]           \
                        + sRed[0][3][p]) * 0.0078125f;                          \
            float d = xv[p] - mu; xv[p] = d;                                    \
            float s = d * d;                                                    \
            _Pragma("unroll")                                                   \
            for (int o = 16; o; o >>= 1) s += __shfl_xor_sync(~0u, s, o);       \
            if (!lane) sRed[1][wid][p] = s;                                     \
        }                                                                       \
        __syncthreads();                                                        \
        float wgt = (lwp)[tid], bia = (lbp)[tid];                               \
        _Pragma("unroll")                                                       \
        for (int p4 = 0; p4 < 4; p4++) {                                        \
            float4 pk;                                                          \
            float* pkf = (float*)&pk;                                           \
            _Pragma("unroll")                                                   \
            for (int j = 0; j < 4; j++) {                                       \
                int p = 4*p4 + j;                                               \
                float var = (sRed[1][0][p] + sRed[1][1][p] + sRed[1][2][p]      \
                             + sRed[1][3][p]) * 0.0078125f;                     \
                pkf[j] = xv[p] * rsqrtf(var + 1e-5f) * wgt + bia;               \
            }                                                                   \
            sYT[tid][p4] = pk;                                                  \
        }                                                                       \
        __syncthreads();                                                        \
    }

// ---------------- LN + qkv -> head-major Q,K,V [b,h,n,16] ------------------
__global__ void __launch_bounds__(128) k_qkvln(
        const float* __restrict__ X, const float* __restrict__ lw,
        const float* __restrict__ lb, const float* __restrict__ W,
        const float* __restrict__ bias,
        float* __restrict__ Qo, float* __restrict__ Ko, float* __restrict__ Vo) {
    int b = blockIdx.y;
    int n0 = blockIdx.x * 16;
    int N = g_N;
    if (n0 >= N) return;
    int tid = threadIdx.x, wid = tid >> 5, lane = tid & 31;
    __shared__ float4 sYT[128][4];
    __shared__ float sRed[2][4][16];
    float xv[16];
    #pragma unroll
    for (int p = 0; p < 16; p++) {
        int n = n0 + p;
        xv[p] = (n < N) ? X[((size_t)b*MAXN + n)*C + tid] : 0.0f;
    }
    LN16_BODY(lw, lb)
    float b0 = bias[tid], b1 = bias[tid + 128], b2 = bias[tid + 256];
    ull a0[8], a1[8], a2[8];
    ull i0 = pack2(b0, b0), i1 = pack2(b1, b1), i2 = pack2(b2, b2);
    #pragma unroll
    for (int j = 0; j < 8; j++) { a0[j] = i0; a1[j] = i1; a2[j] = i2; }
    #pragma unroll 4
    for (int k = 0; k < 128; k++) {
        float w0 = W[k*384 + tid];
        float w1 = W[k*384 + 128 + tid];
        float w2 = W[k*384 + 256 + tid];
        ull w02 = pack2(w0, w0), w12 = pack2(w1, w1), w22 = pack2(w2, w2);
        const ulonglong2* yr = (const ulonglong2*)&sYT[k][0];
        ulonglong2 y0 = yr[0], y1 = yr[1], y2 = yr[2], y3 = yr[3];
        ull yv[8] = {y0.x, y0.y, y1.x, y1.y, y2.x, y2.y, y3.x, y3.y};
        #pragma unroll
        for (int j = 0; j < 8; j++) {
            a0[j] = fma2(w02, yv[j], a0[j]);
            a1[j] = fma2(w12, yv[j], a1[j]);
            a2[j] = fma2(w22, yv[j], a2[j]);
        }
    }
    int h = tid >> 4, d = tid & 15;
    size_t hb = (size_t)(b*NH + h)*MAXN;
    #pragma unroll
    for (int j = 0; j < 8; j++) {
        float2 q2 = unpack2(a0[j]);
        float2 k2 = unpack2(a1[j]);
        float2 v2 = unpack2(a2[j]);
        int n = n0 + 2*j;
        if (n < N) {
            size_t o = (hb + n)*HD + d;
            Qo[o] = q2.x; Ko[o] = k2.x; Vo[o] = v2.x;
        }
        if (n + 1 < N) {
            size_t o = (hb + n + 1)*HD + d;
            Qo[o] = q2.y; Ko[o] = k2.y; Vo[o] = v2.y;
        }
    }
}

// ---------------- attention: 1 query/lane, f32x2 math, block=64 ------------
// grid (17, B*NH), block 64
__global__ void __launch_bounds__(64) k_attn4(
        const float* __restrict__ Q, const float* __restrict__ K,
        const float* __restrict__ V, float* __restrict__ O) {
    int N = g_N;
    int bh = blockIdx.y;
    int b = bh >> 3, h = bh & 7;
    int q0 = blockIdx.x * 64;
    if (q0 >= N) return;
    int tid = threadIdx.x;
    __shared__ float4 sK[TKA*4];
    __shared__ float4 sV[TKA*4];
    const float4* K4 = (const float4*)(K + (size_t)bh*MAXN*HD);
    const float4* V4 = (const float4*)(V + (size_t)bh*MAXN*HD);
    int q = q0 + tid;

    ull qv2[8];
    if (q < N) {
        const float4* Q4 = (const float4*)(Q + ((size_t)bh*MAXN + q)*HD);
        ull qs = pack2(0.25f, 0.25f);   // exact power-of-two prescale
        #pragma unroll
        for (int j = 0; j < 4; j++) {
            float4 t = Q4[j];
            qv2[2*j]   = mul2(pack2(t.x, t.y), qs);
            qv2[2*j+1] = mul2(pack2(t.z, t.w), qs);
        }
    }

    float m_run = -1e30f, l_run = 0.0f;
    ull acc2[8];
    #pragma unroll
    for (int j = 0; j < 8; j++) acc2[j] = 0ull;   // bits of (0.0f,0.0f)

    int nt = (N + TKA - 1) / TKA;
    for (int t = 0; t < nt; t++) {
        int base = t * TKA;
        int kn = min(TKA, N - base);
        __syncthreads();
        for (int i = tid; i < kn*4; i += 64) {
            sK[i] = K4[base*4 + i];
            sV[i] = V4[base*4 + i];
        }
        __syncthreads();
        if (q < N) {
            for (int m = 0; m < kn; m++) {
                const ulonglong2* kp = (const ulonglong2*)&sK[m*4];
                ulonglong2 k0 = kp[0], k1 = kp[1], k2 = kp[2], k3 = kp[3];
                ull sa = fma2(qv2[1], k0.y, mul2(qv2[0], k0.x));
                ull sb = fma2(qv2[3], k1.y, mul2(qv2[2], k1.x));
                ull sc = fma2(qv2[5], k2.y, mul2(qv2[4], k2.x));
                ull sd = fma2(qv2[7], k3.y, mul2(qv2[6], k3.x));
                ull st = add2(add2(sa, sb), add2(sc, sd));
                float2 sp = unpack2(st);
                float s = sp.x + sp.y;
                if (s > m_run) {
                    float corr = __expf(m_run - s);
                    ull c2 = pack2(corr, corr);
                    #pragma unroll
                    for (int j = 0; j < 8; j++) acc2[j] = mul2(acc2[j], c2);
                    l_run *= corr;
                    m_run = s;
                }
                float e = __expf(s - m_run);
                l_run += e;
                ull e2 = pack2(e, e);
                const ulonglong2* vp = (const ulonglong2*)&sV[m*4];
                ulonglong2 v0 = vp[0], v1 = vp[1], v2 = vp[2], v3 = vp[3];
                acc2[0] = fma2(e2, v0.x, acc2[0]);
                acc2[1] = fma2(e2, v0.y, acc2[1]);
                acc2[2] = fma2(e2, v1.x, acc2[2]);
                acc2[3] = fma2(e2, v1.y, acc2[3]);
                acc2[4] = fma2(e2, v2.x, acc2[4]);
                acc2[5] = fma2(e2, v2.y, acc2[5]);
                acc2[6] = fma2(e2, v3.x, acc2[6]);
                acc2[7] = fma2(e2, v3.y, acc2[7]);
            }
        }
    }

    if (q < N) {
        float inv = 1.0f / l_run;
        // CLS-key probability: recompute score vs key 0 (same op order)
        {
            const ulonglong2* kp = (const ulonglong2*)K4;
            ulonglong2 k0 = kp[0], k1 = kp[1], k2 = kp[2], k3 = kp[3];
            ull sa = fma2(qv2[1], k0.y, mul2(qv2[0], k0.x));
            ull sb = fma2(qv2[3], k1.y, mul2(qv2[2], k1.x));
            ull sc = fma2(qv2[5], k2.y, mul2(qv2[4], k2.x));
            ull sd = fma2(qv2[7], k3.y, mul2(qv2[6], k3.x));
            ull st = add2(add2(sa, sb), add2(sc, sd));
            float2 sp = unpack2(st);
            float s0 = sp.x + sp.y;
            g_CLSP[(size_t)bh*MAXN + q] = __expf(s0 - m_run) * inv;
        }
        float* op = O + ((size_t)b*MAXN + q)*C + h*HD;
        #pragma unroll
        for (int j = 0; j < 4; j++) {
            float2 u0 = unpack2(acc2[2*j]);
            float2 u1 = unpack2(acc2[2*j+1]);
            ((float4*)op)[j] = make_float4(u0.x*inv, u0.y*inv, u1.x*inv, u1.y*inv);
        }
    }
}

// ---------------- out proj: X += O @ W(128x128) + b (16 tokens) ------------
__global__ void __launch_bounds__(128) k_proj(
        const float* __restrict__ Oin, const float* __restrict__ W,
        const float* __restrict__ bias, float* __restrict__ X) {
    int b = blockIdx.y;
    int n0 = blockIdx.x * 16;
    int N = g_N;
    if (n0 >= N) return;
    int tid = threadIdx.x;
    __shared__ __align__(16) float sOT[128][16];
    const float4* O4 = (const float4*)Oin;
    for (int v = tid; v < 16*32; v += 128) {
        int p = v & 15, kq = v >> 4;
        int n = n0 + p;
        float4 o4 = (n < N) ? O4[((size_t)b*MAXN + n)*32 + kq]
                            : make_float4(0.f, 0.f, 0.f, 0.f);
        sOT[4*kq+0][p] = o4.x; sOT[4*kq+1][p] = o4.y;
        sOT[4*kq+2][p] = o4.z; sOT[4*kq+3][p] = o4.w;
    }
    __syncthreads();
    float bs = bias[tid];
    ull acc2[8];
    ull bini = pack2(bs, bs);
    #pragma unroll
    for (int j = 0; j < 8; j++) acc2[j] = bini;
    #pragma unroll 4
    for (int k = 0; k < 128; k++) {
        float w = W[k*128 + tid];
        ull w2 = pack2(w, w);
        const ulonglong2* yr = (const ulonglong2*)&sOT[k][0];
        ulonglong2 y0 = yr[0], y1 = yr[1], y2 = yr[2], y3 = yr[3];
        acc2[0] = fma2(w2, y0.x, acc2[0]); acc2[1] = fma2(w2, y0.y, acc2[1]);
        acc2[2] = fma2(w2, y1.x, acc2[2]); acc2[3] = fma2(w2, y1.y, acc2[3]);
        acc2[4] = fma2(w2, y2.x, acc2[4]); acc2[5] = fma2(w2, y2.y, acc2[5]);
        acc2[6] = fma2(w2, y3.x, acc2[6]); acc2[7] = fma2(w2, y3.y, acc2[7]);
    }
    #pragma unroll
    for (int j = 0; j < 8; j++) {
        float2 u = unpack2(acc2[j]);
        int n = n0 + 2*j;
        if (n < N)     X[((size_t)b*MAXN + n)*C + tid]     += u.x;
        if (n + 1 < N) X[((size_t)b*MAXN + n + 1)*C + tid] += u.y;
    }
}

// ---------------- LN + fc1 + exact gelu (16 tokens, 4 cols/thread) ---------
__global__ void __launch_bounds__(128) k_fc1ln(
        const float* __restrict__ X, const float* __restrict__ lw,
        const float* __restrict__ lb, const float* __restrict__ W,
        const float* __restrict__ bias, float* __restrict__ H) {
    int b = blockIdx.y;
    int n0 = blockIdx.x * 16;
    int N = g_N;
    if (n0 >= N) return;
    int tid = threadIdx.x, wid = tid >> 5, lane = tid & 31;
    __shared__ float4 sYT[128][4];
    __shared__ float sRed[2][4][16];
    float xv[16];
    #pragma unroll
    for (int p = 0; p < 16; p++) {
        int n = n0 + p;
        xv[p] = (n < N) ? X[((size_t)b*MAXN + n)*C + tid] : 0.0f;
    }
    LN16_BODY(lw, lb)
    const float4* W4 = (const float4*)W;
    float4 b4 = ((const float4*)bias)[tid];
    ull a0[8], a1[8], a2[8], a3[8];
    ull i0 = pack2(b4.x, b4.x), i1 = pack2(b4.y, b4.y);
    ull i2 = pack2(b4.z, b4.z), i3 = pack2(b4.w, b4.w);
    #pragma unroll
    for (int j = 0; j < 8; j++) { a0[j]=i0; a1[j]=i1; a2[j]=i2; a3[j]=i3; }
    #pragma unroll 2
    for (int k = 0; k < 128; k++) {
        float4 w4 = W4[k*128 + tid];
        ull w0 = pack2(w4.x, w4.x), w1 = pack2(w4.y, w4.y);
        ull w2 = pack2(w4.z, w4.z), w3 = pack2(w4.w, w4.w);
        const ulonglong2* yr = (const ulonglong2*)&sYT[k][0];
        ulonglong2 y0 = yr[0], y1 = yr[1], y2 = yr[2], y3 = yr[3];
        ull yv[8] = {y0.x, y0.y, y1.x, y1.y, y2.x, y2.y, y3.x, y3.y};
        #pragma unroll
        for (int j = 0; j < 8; j++) {
            a0[j] = fma2(w0, yv[j], a0[j]);
            a1[j] = fma2(w1, yv[j], a1[j]);
            a2[j] = fma2(w2, yv[j], a2[j]);
            a3[j] = fma2(w3, yv[j], a3[j]);
        }
    }
    float4* H4 = (float4*)H;
    #pragma unroll
    for (int j = 0; j < 8; j++) {
        float2 u0 = unpack2(a0[j]);
        float2 u1 = unpack2(a1[j]);
        float2 u2 = unpack2(a2[j]);
        float2 u3 = unpack2(a3[j]);
        int n = n0 + 2*j;
        if (n < N) {
            float4 hv;
            hv.x = 0.5f*u0.x*(1.0f + erff(u0.x*0.70710678118654752f));
            hv.y = 0.5f*u1.x*(1.0f + erff(u1.x*0.70710678118654752f));
            hv.z = 0.5f*u2.x*(1.0f + erff(u2.x*0.70710678118654752f));
            hv.w = 0.5f*u3.x*(1.0f + erff(u3.x*0.70710678118654752f));
            H4[((size_t)b*MAXN + n)*128 + tid] = hv;
        }
        if (n + 1 < N) {
            float4 hv;
            hv.x = 0.5f*u0.y*(1.0f + erff(u0.y*0.70710678118654752f));
            hv.y = 0.5f*u1.y*(1.0f + erff(u1.y*0.70710678118654752f));
            hv.z = 0.5f*u2.y*(1.0f + erff(u2.y*0.70710678118654752f));
            hv.w = 0.5f*u3.y*(1.0f + erff(u3.y*0.70710678118654752f));
            H4[((size_t)b*MAXN + n + 1)*128 + tid] = hv;
        }
    }
}

// ---------------- fc2: X += H @ W2(512x128) + b2 (16 tokens) ---------------
__global__ void __launch_bounds__(128) k_fc2(
        const float* __restrict__ H, const float* __restrict__ W,
        const float* __restrict__ bias, float* __restrict__ X) {
    int b = blockIdx.y;
    int n0 = blockIdx.x * 16;
    int N = g_N;
    if (n0 >= N) return;
    int tid = threadIdx.x;
    __shared__ __align__(16) float sHT[512][16];   // 32KB
    const float4* H4 = (const float4*)H;
    for (int v = tid; v < 16*128; v += 128) {
        int p = v & 15, kq = v >> 4;
        int n = n0 + p;
        float4 h4 = (n < N) ? H4[((size_t)b*MAXN + n)*128 + kq]
                            : make_float4(0.f, 0.f, 0.f, 0.f);
        sHT[4*kq+0][p] = h4.x; sHT[4*kq+1][p] = h4.y;
        sHT[4*kq+2][p] = h4.z; sHT[4*kq+3][p] = h4.w;
    }
    __syncthreads();
    float bs = bias[tid];
    ull acc2[8];
    ull bini = pack2(bs, bs);
    #pragma unroll
    for (int j = 0; j < 8; j++) acc2[j] = bini;
    #pragma unroll 4
    for (int k = 0; k < 512; k++) {
        float w = W[k*128 + tid];
        ull w2 = pack2(w, w);
        const ulonglong2* yr = (const ulonglong2*)&sHT[k][0];
        ulonglong2 y0 = yr[0], y1 = yr[1], y2 = yr[2], y3 = yr[3];
        acc2[0] = fma2(w2, y0.x, acc2[0]); acc2[1] = fma2(w2, y0.y, acc2[1]);
        acc2[2] = fma2(w2, y1.x, acc2[2]); acc2[3] = fma2(w2, y1.y, acc2[3]);
        acc2[4] = fma2(w2, y2.x, acc2[4]); acc2[5] = fma2(w2, y2.y, acc2[5]);
        acc2[6] = fma2(w2, y3.x, acc2[6]); acc2[7] = fma2(w2, y3.y, acc2[7]);
    }
    #pragma unroll
    for (int j = 0; j < 8; j++) {
        float2 u = unpack2(acc2[j]);
        int n = n0 + 2*j;
        if (n < N)     X[((size_t)b*MAXN + n)*C + tid]     += u.x;
        if (n + 1 < N) X[((size_t)b*MAXN + n + 1)*C + tid] += u.y;
    }
}

// ---------------- prune stage 1 ---------------------------------------------
__global__ void k_prune1(float thresh, int pi) {
    int b = blockIdx.x;
    int t = threadIdx.x;
    int tc = g_N - 1;
    __shared__ int ssum[1024];
    __shared__ float sval[1024];
    __shared__ int sidx[1024];
    float am = -1e30f;
    int keep = 0;
    if (t < tc) {
        float s = 0.0f;
        #pragma unroll
        for (int h = 0; h < NH; h++) s += g_CLSP[(b*NH + h)*MAXN + 1 + t];
        am = s * 0.125f;
        keep = (am > thresh) ? 1 : 0;
    }
    ssum[t] = keep; sval[t] = am; sidx[t] = t;
    __syncthreads();
    for (int off = 512; off > 0; off >>= 1) {
        if (t < off) {
            if (sval[t + off] > sval[t] ||
                (sval[t + off] == sval[t] && sidx[t + off] < sidx[t])) {
                sval[t] = sval[t + off]; sidx[t] = sidx[t + off];
            }
        }
        __syncthreads();
    }
    int argidx = sidx[0];
    __syncthreads();
    for (int off = 1; off < 1024; off <<= 1) {
        int v = (t >= off) ? ssum[t - off] : 0;
        __syncthreads();
        ssum[t] += v;
        __syncthreads();
    }
    int total = ssum[1023];
    if (total > 0 && keep) g_order[b][ssum[t] - 1] = t;
    if (t == 0) {
        int cnt = total;
        if (total == 0) { g_order[b][0] = argidx; cnt = 1; }
        g_count[b] = cnt;
        atomicMax(&g_mk[pi], cnt);
    }
}

// ---------------- prune stage 2 ---------------------------------------------
__global__ void k_prune2(const float* __restrict__ Xold, float* __restrict__ Xnew,
                         const float* __restrict__ pos, int pi) {
    int b = blockIdx.y, c = threadIdx.x;
    int mk = g_mk[pi];
    if (blockIdx.x == 0) {
        Xnew[(size_t)b*MAXN*C + c] = Xold[(size_t)b*MAXN*C + c] + pos[c];
        if (b == 0 && c == 0) g_N = 1 + mk;
        return;
    }
    int j = blockIdx.x - 1;
    if (j >= mk) return;
    float v = 0.0f;
    if (j < g_count[b]) {
        int src = g_order[b][j];
        v = Xold[((size_t)b*MAXN + 1 + src)*C + c];
    }
    Xnew[((size_t)b*MAXN + 1 + j)*C + c] = v + pos[(1 + j)*C + c];
}

// ---------------- output copy ----------------------------------------------
__global__ void k_copy(const float* __restrict__ X, float* __restrict__ out,
                       int finalN, int total) {
    int idx = blockIdx.x * 256 + threadIdx.x;
    if (idx >= total) return;
    int per = finalN * C;
    int b = idx / per;
    int rem = idx - b * per;
    out[idx] = X[(size_t)b*MAXN*C + rem];
}

// ---------------- host orchestration ----------------------------------------
extern "C" void kernel_launch(void* const* d_in, const int* in_sizes, int n_in,
                              void* d_out, int out_size) {
    const float* conv_w   = (const float*)d_in[0];
    const float* conv_b   = (const float*)d_in[1];
    const float* cls_tok  = (const float*)d_in[2];
    const float* pos      = (const float*)d_in[3];
    const float* ln1_w    = (const float*)d_in[4];
    const float* ln1_b    = (const float*)d_in[5];
    const float* qkv_w    = (const float*)d_in[6];
    const float* qkv_b    = (const float*)d_in[7];
    const float* out_w    = (const float*)d_in[8];
    const float* out_b    = (const float*)d_in[9];
    const float* ln2_w    = (const float*)d_in[10];
    const float* ln2_b    = (const float*)d_in[11];
    const float* mlp_w1   = (const float*)d_in[12];
    const float* mlp_b1   = (const float*)d_in[13];
    const float* mlp_w2   = (const float*)d_in[14];
    const float* mlp_b2   = (const float*)d_in[15];
    const float* x        = (const float*)d_in[16];
    float* out = (float*)d_out;

    float *pX0, *pX1, *pQ, *pK, *pV, *pO, *pH;
    cudaGetSymbolAddress((void**)&pX0, g_X0);
    cudaGetSymbolAddress((void**)&pX1, g_X1);
    cudaGetSymbolAddress((void**)&pQ,  g_Q);
    cudaGetSymbolAddress((void**)&pK,  g_K);
    cudaGetSymbolAddress((void**)&pV,  g_V);
    cudaGetSymbolAddress((void**)&pO,  g_O);
    cudaGetSymbolAddress((void**)&pH,  g_H);

    const float THRESH[3] = {0.001f, 0.0012f, 0.0015f};

    k_transpose<<<768, 128>>>(conv_w);
    k_patch<<<dim3(65, BATCH), 128>>>(x, conv_b, cls_tok, pos, pX0);

    float* cur = pX0;
    float* alt = pX1;
    dim3 gBlk(65, BATCH);
    dim3 gAtt((MAXN + 63)/64, BATCH*NH);
    dim3 gTok(MAXN, BATCH);

    for (int i = 0; i < L; i++) {
        k_qkvln<<<gBlk, 128>>>(cur, ln1_w + i*C, ln1_b + i*C,
                               qkv_w + (size_t)i*C*384, qkv_b + i*384, pQ, pK, pV);
        k_attn4<<<gAtt, 64>>>(pQ, pK, pV, pO);
        k_proj <<<gBlk, 128>>>(pO, out_w + (size_t)i*C*C, out_b + i*C, cur);
        k_fc1ln<<<gBlk, 128>>>(cur, ln2_w + i*C, ln2_b + i*C,
                               mlp_w1 + (size_t)i*C*512, mlp_b1 + i*512, pH);
        k_fc2  <<<gBlk, 128>>>(pH, mlp_w2 + (size_t)i*512*C, mlp_b2 + i*C, cur);
        if (i < L - 1) {
            k_prune1<<<BATCH, 1024>>>(THRESH[i], i);
            k_prune2<<<gTok, 128>>>(cur, alt, pos, i);
            float* tmp = cur; cur = alt; alt = tmp;
        }
    }

    int finalN = out_size / (BATCH * C);
    int nblk = (out_size + 255) / 256;
    k_copy<<<nblk, 256>>>(cur, out, finalN, out_size);
}

// round 5
// speedup vs baseline: 1.1055x; 1.1055x over previous
#include <cuda_runtime.h>
#include <math.h>

#define MAXN 1025
#define BATCH 8
#define C 128
#define NH 8
#define HD 16
#define L 4
#define TKA 128

typedef unsigned long long ull;

// ---------------- packed fp32x2 helpers (sm_103a FFMA2 path) ---------------
__device__ __forceinline__ ull pack2(float lo, float hi) {
    ull r; asm("mov.b64 %0, {%1, %2};" : "=l"(r) : "f"(lo), "f"(hi)); return r;
}
__device__ __forceinline__ float2 unpack2(ull v) {
    float lo, hi; asm("mov.b64 {%0, %1}, %2;" : "=f"(lo), "=f"(hi) : "l"(v));
    return make_float2(lo, hi);
}
__device__ __forceinline__ ull fma2(ull a, ull b, ull c) {
    ull d; asm("fma.rn.f32x2 %0, %1, %2, %3;" : "=l"(d) : "l"(a), "l"(b), "l"(c));
    return d;
}
__device__ __forceinline__ ull mul2(ull a, ull b) {
    ull d; asm("mul.rn.f32x2 %0, %1, %2;" : "=l"(d) : "l"(a), "l"(b));
    return d;
}
__device__ __forceinline__ ull add2(ull a, ull b) {
    ull d; asm("add.rn.f32x2 %0, %1, %2;" : "=l"(d) : "l"(a), "l"(b));
    return d;
}

// ---------------- device scratch (static, allocation-free) ----------------
__device__ float g_X0[BATCH*MAXN*C];
__device__ float g_X1[BATCH*MAXN*C];
__device__ float g_Q [BATCH*NH*MAXN*HD];
__device__ float g_K [BATCH*NH*MAXN*HD];
__device__ float g_V [BATCH*NH*MAXN*HD];
__device__ float g_O [BATCH*MAXN*C];
__device__ float g_H [BATCH*MAXN*512];
__device__ float g_CLSP[BATCH*NH*MAXN];
__device__ float g_WT[768*128];
__device__ int   g_order[BATCH][1024];
__device__ int   g_count[BATCH];
__device__ int   g_mk[3];
__device__ int   g_N;

// transpose conv_w (128,768) -> (768,128); also does global init
__global__ void k_transpose(const float* __restrict__ w) {
    int k = blockIdx.x, c = threadIdx.x;
    g_WT[k*128 + c] = w[c*768 + k];
    if (k == 0 && c == 0) {
        g_N = MAXN;
        g_mk[0] = 0; g_mk[1] = 0; g_mk[2] = 0;
    }
}

// ---------------- patch embed + cls row ------------------------------------
__global__ void __launch_bounds__(128) k_patch(
        const float* __restrict__ x, const float* __restrict__ cb,
        const float* __restrict__ cls, const float* __restrict__ pos,
        float* __restrict__ X) {
    int b = blockIdx.y;
    int tid = threadIdx.x;
    if (blockIdx.x == 64) {
        X[(size_t)b*MAXN*C + tid] = cls[tid] + pos[tid];
        return;
    }
    int t0 = blockIdx.x * 16;
    __shared__ __align__(16) float sPT[768][16];
    for (int v = tid; v < 768*16; v += 128) {
        int p = v & 15, k = v >> 4;
        int t = t0 + p;
        int ph = t >> 5, pw = t & 31;
        int ch = k >> 8, rem = k & 255, py = rem >> 4, px = rem & 15;
        sPT[k][p] = x[((size_t)(b*3 + ch)*512 + ph*16 + py)*512 + pw*16 + px];
    }
    __syncthreads();
    float bias = cb[tid];
    ull acc2[8];
    ull bini = pack2(bias, bias);
    #pragma unroll
    for (int j = 0; j < 8; j++) acc2[j] = bini;
    #pragma unroll 4
    for (int k = 0; k < 768; k++) {
        float w = g_WT[k*128 + tid];
        ull w2 = pack2(w, w);
        const ulonglong2* yr = (const ulonglong2*)&sPT[k][0];
        ulonglong2 y0 = yr[0], y1 = yr[1], y2 = yr[2], y3 = yr[3];
        acc2[0] = fma2(w2, y0.x, acc2[0]); acc2[1] = fma2(w2, y0.y, acc2[1]);
        acc2[2] = fma2(w2, y1.x, acc2[2]); acc2[3] = fma2(w2, y1.y, acc2[3]);
        acc2[4] = fma2(w2, y2.x, acc2[4]); acc2[5] = fma2(w2, y2.y, acc2[5]);
        acc2[6] = fma2(w2, y3.x, acc2[6]); acc2[7] = fma2(w2, y3.y, acc2[7]);
    }
    #pragma unroll
    for (int j = 0; j < 8; j++) {
        float2 u = unpack2(acc2[j]);
        int t = t0 + 2*j;
        X[((size_t)b*MAXN + 1 + t)*C + tid]     = u.x + pos[(1 + t)*C + tid];
        X[((size_t)b*MAXN + 2 + t)*C + tid]     = u.y + pos[(2 + t)*C + tid];
    }
}

// ---------------- LN helper (16 tokens, 128 threads) -----------------------
#define LN16_BODY(lwp, lbp)                                                     \
    {                                                                           \
        _Pragma("unroll")                                                       \
        for (int p = 0; p < 16; p++) {                                          \
            float s = xv[p];                                                    \
            _Pragma("unroll")                                                   \
            for (int o = 16; o; o >>= 1) s += __shfl_xor_sync(~0u, s, o);       \
            if (!lane) sRed[0][wid][p] = s;                                     \
        }                                                                       \
        __syncthreads();                                                        \
        _Pragma("unroll")                                                       \
        for (int p = 0; p < 16; p++) {                                          \
            float mu = (sRed[0][0][p] + sRed[0][1][p] + sRed[0][2][p]           \
                        + sRed[0][3][p]) * 0.0078125f;                          \
            float d = xv[p] - mu; xv[p] = d;                                    \
            float s = d * d;                                                    \
            _Pragma("unroll")                                                   \
            for (int o = 16; o; o >>= 1) s += __shfl_xor_sync(~0u, s, o);       \
            if (!lane) sRed[1][wid][p] = s;                                     \
        }                                                                       \
        __syncthreads();                                                        \
        float wgt = (lwp)[tid], bia = (lbp)[tid];                               \
        _Pragma("unroll")                                                       \
        for (int p4 = 0; p4 < 4; p4++) {                                        \
            float4 pk;                                                          \
            float* pkf = (float*)&pk;                                           \
            _Pragma("unroll")                                                   \
            for (int j = 0; j < 4; j++) {                                       \
                int p = 4*p4 + j;                                               \
                float var = (sRed[1][0][p] + sRed[1][1][p] + sRed[1][2][p]      \
                             + sRed[1][3][p]) * 0.0078125f;                     \
                pkf[j] = xv[p] * rsqrtf(var + 1e-5f) * wgt + bia;               \
            }                                                                   \
            sYT[tid][p4] = pk;                                                  \
        }                                                                       \
        __syncthreads();                                                        \
    }

// ---------------- LN + qkv -> head-major Q,K,V [b,h,n,16] ------------------
__global__ void __launch_bounds__(128) k_qkvln(
        const float* __restrict__ X, const float* __restrict__ lw,
        const float* __restrict__ lb, const float* __restrict__ W,
        const float* __restrict__ bias,
        float* __restrict__ Qo, float* __restrict__ Ko, float* __restrict__ Vo) {
    int b = blockIdx.y;
    int n0 = blockIdx.x * 16;
    int N = g_N;
    if (n0 >= N) return;
    int tid = threadIdx.x, wid = tid >> 5, lane = tid & 31;
    __shared__ float4 sYT[128][4];
    __shared__ float sRed[2][4][16];
    float xv[16];
    #pragma unroll
    for (int p = 0; p < 16; p++) {
        int n = n0 + p;
        xv[p] = (n < N) ? X[((size_t)b*MAXN + n)*C + tid] : 0.0f;
    }
    LN16_BODY(lw, lb)
    float b0 = bias[tid], b1 = bias[tid + 128], b2 = bias[tid + 256];
    ull a0[8], a1[8], a2[8];
    ull i0 = pack2(b0, b0), i1 = pack2(b1, b1), i2 = pack2(b2, b2);
    #pragma unroll
    for (int j = 0; j < 8; j++) { a0[j] = i0; a1[j] = i1; a2[j] = i2; }
    #pragma unroll 4
    for (int k = 0; k < 128; k++) {
        float w0 = W[k*384 + tid];
        float w1 = W[k*384 + 128 + tid];
        float w2 = W[k*384 + 256 + tid];
        ull w02 = pack2(w0, w0), w12 = pack2(w1, w1), w22 = pack2(w2, w2);
        const ulonglong2* yr = (const ulonglong2*)&sYT[k][0];
        ulonglong2 y0 = yr[0], y1 = yr[1], y2 = yr[2], y3 = yr[3];
        ull yv[8] = {y0.x, y0.y, y1.x, y1.y, y2.x, y2.y, y3.x, y3.y};
        #pragma unroll
        for (int j = 0; j < 8; j++) {
            a0[j] = fma2(w02, yv[j], a0[j]);
            a1[j] = fma2(w12, yv[j], a1[j]);
            a2[j] = fma2(w22, yv[j], a2[j]);
        }
    }
    int h = tid >> 4, d = tid & 15;
    size_t hb = (size_t)(b*NH + h)*MAXN;
    #pragma unroll
    for (int j = 0; j < 8; j++) {
        float2 q2 = unpack2(a0[j]);
        float2 k2 = unpack2(a1[j]);
        float2 v2 = unpack2(a2[j]);
        int n = n0 + 2*j;
        if (n < N) {
            size_t o = (hb + n)*HD + d;
            Qo[o] = q2.x; Ko[o] = k2.x; Vo[o] = v2.x;
        }
        if (n + 1 < N) {
            size_t o = (hb + n + 1)*HD + d;
            Qo[o] = q2.y; Ko[o] = k2.y; Vo[o] = v2.y;
        }
    }
}

// ---------------- attention v5: no-max softmax, f32x2, block=128 ------------
// Scores are bounded (|s| <~ 10 with LN'd activations), so exp() cannot
// overflow fp32; skipping the max-subtraction only changes rounding.
// grid (9, B*NH), block 128
__global__ void __launch_bounds__(128) k_attn5(
        const float* __restrict__ Q, const float* __restrict__ K,
        const float* __restrict__ V, float* __restrict__ O) {
    int N = g_N;
    int bh = blockIdx.y;
    int b = bh >> 3, h = bh & 7;
    int q0 = blockIdx.x * 128;
    if (q0 >= N) return;
    int tid = threadIdx.x;
    __shared__ float4 sK[TKA*4];
    __shared__ float4 sV[TKA*4];
    const float4* K4 = (const float4*)(K + (size_t)bh*MAXN*HD);
    const float4* V4 = (const float4*)(V + (size_t)bh*MAXN*HD);
    int q = q0 + tid;

    ull qv2[8];
    if (q < N) {
        const float4* Q4 = (const float4*)(Q + ((size_t)bh*MAXN + q)*HD);
        ull qs = pack2(0.25f, 0.25f);   // exact power-of-two prescale
        #pragma unroll
        for (int j = 0; j < 4; j++) {
            float4 t = Q4[j];
            qv2[2*j]   = mul2(pack2(t.x, t.y), qs);
            qv2[2*j+1] = mul2(pack2(t.z, t.w), qs);
        }
    }

    float l_run = 0.0f;
    ull acc2[8];
    #pragma unroll
    for (int j = 0; j < 8; j++) acc2[j] = 0ull;

    int nt = (N + TKA - 1) / TKA;
    for (int t = 0; t < nt; t++) {
        int base = t * TKA;
        int kn = min(TKA, N - base);
        __syncthreads();
        for (int i = tid; i < kn*4; i += 128) {
            sK[i] = K4[base*4 + i];
            sV[i] = V4[base*4 + i];
        }
        __syncthreads();
        if (q < N) {
            #pragma unroll 2
            for (int m = 0; m < kn; m++) {
                const ulonglong2* kp = (const ulonglong2*)&sK[m*4];
                ulonglong2 k0 = kp[0], k1 = kp[1], k2 = kp[2], k3 = kp[3];
                ull sa = fma2(qv2[1], k0.y, mul2(qv2[0], k0.x));
                ull sb = fma2(qv2[3], k1.y, mul2(qv2[2], k1.x));
                ull sc = fma2(qv2[5], k2.y, mul2(qv2[4], k2.x));
                ull sd = fma2(qv2[7], k3.y, mul2(qv2[6], k3.x));
                ull st = add2(add2(sa, sb), add2(sc, sd));
                float2 sp = unpack2(st);
                float e = __expf(sp.x + sp.y);
                l_run += e;
                ull e2 = pack2(e, e);
                const ulonglong2* vp = (const ulonglong2*)&sV[m*4];
                ulonglong2 v0 = vp[0], v1 = vp[1], v2 = vp[2], v3 = vp[3];
                acc2[0] = fma2(e2, v0.x, acc2[0]);
                acc2[1] = fma2(e2, v0.y, acc2[1]);
                acc2[2] = fma2(e2, v1.x, acc2[2]);
                acc2[3] = fma2(e2, v1.y, acc2[3]);
                acc2[4] = fma2(e2, v2.x, acc2[4]);
                acc2[5] = fma2(e2, v2.y, acc2[5]);
                acc2[6] = fma2(e2, v3.x, acc2[6]);
                acc2[7] = fma2(e2, v3.y, acc2[7]);
            }
        }
    }

    if (q < N) {
        float inv = 1.0f / l_run;
        // CLS-key probability: recompute score vs key 0 (same op order)
        {
            const ulonglong2* kp = (const ulonglong2*)K4;
            ulonglong2 k0 = kp[0], k1 = kp[1], k2 = kp[2], k3 = kp[3];
            ull sa = fma2(qv2[1], k0.y, mul2(qv2[0], k0.x));
            ull sb = fma2(qv2[3], k1.y, mul2(qv2[2], k1.x));
            ull sc = fma2(qv2[5], k2.y, mul2(qv2[4], k2.x));
            ull sd = fma2(qv2[7], k3.y, mul2(qv2[6], k3.x));
            ull st = add2(add2(sa, sb), add2(sc, sd));
            float2 sp = unpack2(st);
            g_CLSP[(size_t)bh*MAXN + q] = __expf(sp.x + sp.y) * inv;
        }
        float* op = O + ((size_t)b*MAXN + q)*C + h*HD;
        #pragma unroll
        for (int j = 0; j < 4; j++) {
            float2 u0 = unpack2(acc2[2*j]);
            float2 u1 = unpack2(acc2[2*j+1]);
            ((float4*)op)[j] = make_float4(u0.x*inv, u0.y*inv, u1.x*inv, u1.y*inv);
        }
    }
}

// ---------------- out proj: X += O @ W(128x128) + b (16 tokens) ------------
__global__ void __launch_bounds__(128) k_proj(
        const float* __restrict__ Oin, const float* __restrict__ W,
        const float* __restrict__ bias, float* __restrict__ X) {
    int b = blockIdx.y;
    int n0 = blockIdx.x * 16;
    int N = g_N;
    if (n0 >= N) return;
    int tid = threadIdx.x;
    __shared__ __align__(16) float sOT[128][16];
    const float4* O4 = (const float4*)Oin;
    for (int v = tid; v < 16*32; v += 128) {
        int p = v & 15, kq = v >> 4;
        int n = n0 + p;
        float4 o4 = (n < N) ? O4[((size_t)b*MAXN + n)*32 + kq]
                            : make_float4(0.f, 0.f, 0.f, 0.f);
        sOT[4*kq+0][p] = o4.x; sOT[4*kq+1][p] = o4.y;
        sOT[4*kq+2][p] = o4.z; sOT[4*kq+3][p] = o4.w;
    }
    __syncthreads();
    float bs = bias[tid];
    ull acc2[8];
    ull bini = pack2(bs, bs);
    #pragma unroll
    for (int j = 0; j < 8; j++) acc2[j] = bini;
    #pragma unroll 4
    for (int k = 0; k < 128; k++) {
        float w = W[k*128 + tid];
        ull w2 = pack2(w, w);
        const ulonglong2* yr = (const ulonglong2*)&sOT[k][0];
        ulonglong2 y0 = yr[0], y1 = yr[1], y2 = yr[2], y3 = yr[3];
        acc2[0] = fma2(w2, y0.x, acc2[0]); acc2[1] = fma2(w2, y0.y, acc2[1]);
        acc2[2] = fma2(w2, y1.x, acc2[2]); acc2[3] = fma2(w2, y1.y, acc2[3]);
        acc2[4] = fma2(w2, y2.x, acc2[4]); acc2[5] = fma2(w2, y2.y, acc2[5]);
        acc2[6] = fma2(w2, y3.x, acc2[6]); acc2[7] = fma2(w2, y3.y, acc2[7]);
    }
    #pragma unroll
    for (int j = 0; j < 8; j++) {
        float2 u = unpack2(acc2[j]);
        int n = n0 + 2*j;
        if (n < N)     X[((size_t)b*MAXN + n)*C + tid]     += u.x;
        if (n + 1 < N) X[((size_t)b*MAXN + n + 1)*C + tid] += u.y;
    }
}

// ---------------- LN + fc1 + exact gelu (16 tokens, 4 cols/thread) ---------
__global__ void __launch_bounds__(128) k_fc1ln(
        const float* __restrict__ X, const float* __restrict__ lw,
        const float* __restrict__ lb, const float* __restrict__ W,
        const float* __restrict__ bias, float* __restrict__ H) {
    int b = blockIdx.y;
    int n0 = blockIdx.x * 16;
    int N = g_N;
    if (n0 >= N) return;
    int tid = threadIdx.x, wid = tid >> 5, lane = tid & 31;
    __shared__ float4 sYT[128][4];
    __shared__ float sRed[2][4][16];
    float xv[16];
    #pragma unroll
    for (int p = 0; p < 16; p++) {
        int n = n0 + p;
        xv[p] = (n < N) ? X[((size_t)b*MAXN + n)*C + tid] : 0.0f;
    }
    LN16_BODY(lw, lb)
    const float4* W4 = (const float4*)W;
    float4 b4 = ((const float4*)bias)[tid];
    ull a0[8], a1[8], a2[8], a3[8];
    ull i0 = pack2(b4.x, b4.x), i1 = pack2(b4.y, b4.y);
    ull i2 = pack2(b4.z, b4.z), i3 = pack2(b4.w, b4.w);
    #pragma unroll
    for (int j = 0; j < 8; j++) { a0[j]=i0; a1[j]=i1; a2[j]=i2; a3[j]=i3; }
    #pragma unroll 2
    for (int k = 0; k < 128; k++) {
        float4 w4 = W4[k*128 + tid];
        ull w0 = pack2(w4.x, w4.x), w1 = pack2(w4.y, w4.y);
        ull w2 = pack2(w4.z, w4.z), w3 = pack2(w4.w, w4.w);
        const ulonglong2* yr = (const ulonglong2*)&sYT[k][0];
        ulonglong2 y0 = yr[0], y1 = yr[1], y2 = yr[2], y3 = yr[3];
        ull yv[8] = {y0.x, y0.y, y1.x, y1.y, y2.x, y2.y, y3.x, y3.y};
        #pragma unroll
        for (int j = 0; j < 8; j++) {
            a0[j] = fma2(w0, yv[j], a0[j]);
            a1[j] = fma2(w1, yv[j], a1[j]);
            a2[j] = fma2(w2, yv[j], a2[j]);
            a3[j] = fma2(w3, yv[j], a3[j]);
        }
    }
    float4* H4 = (float4*)H;
    #pragma unroll
    for (int j = 0; j < 8; j++) {
        float2 u0 = unpack2(a0[j]);
        float2 u1 = unpack2(a1[j]);
        float2 u2 = unpack2(a2[j]);
        float2 u3 = unpack2(a3[j]);
        int n = n0 + 2*j;
        if (n < N) {
            float4 hv;
            hv.x = 0.5f*u0.x*(1.0f + erff(u0.x*0.70710678118654752f));
            hv.y = 0.5f*u1.x*(1.0f + erff(u1.x*0.70710678118654752f));
            hv.z = 0.5f*u2.x*(1.0f + erff(u2.x*0.70710678118654752f));
            hv.w = 0.5f*u3.x*(1.0f + erff(u3.x*0.70710678118654752f));
            H4[((size_t)b*MAXN + n)*128 + tid] = hv;
        }
        if (n + 1 < N) {
            float4 hv;
            hv.x = 0.5f*u0.y*(1.0f + erff(u0.y*0.70710678118654752f));
            hv.y = 0.5f*u1.y*(1.0f + erff(u1.y*0.70710678118654752f));
            hv.z = 0.5f*u2.y*(1.0f + erff(u2.y*0.70710678118654752f));
            hv.w = 0.5f*u3.y*(1.0f + erff(u3.y*0.70710678118654752f));
            H4[((size_t)b*MAXN + n + 1)*128 + tid] = hv;
        }
    }
}

// ---------------- fc2: X += H @ W2(512x128) + b2 (16 tokens) ---------------
__global__ void __launch_bounds__(128) k_fc2(
        const float* __restrict__ H, const float* __restrict__ W,
        const float* __restrict__ bias, float* __restrict__ X) {
    int b = blockIdx.y;
    int n0 = blockIdx.x * 16;
    int N = g_N;
    if (n0 >= N) return;
    int tid = threadIdx.x;
    __shared__ __align__(16) float sHT[512][16];   // 32KB
    const float4* H4 = (const float4*)H;
    for (int v = tid; v < 16*128; v += 128) {
        int p = v & 15, kq = v >> 4;
        int n = n0 + p;
        float4 h4 = (n < N) ? H4[((size_t)b*MAXN + n)*128 + kq]
                            : make_float4(0.f, 0.f, 0.f, 0.f);
        sHT[4*kq+0][p] = h4.x; sHT[4*kq+1][p] = h4.y;
        sHT[4*kq+2][p] = h4.z; sHT[4*kq+3][p] = h4.w;
    }
    __syncthreads();
    float bs = bias[tid];
    ull acc2[8];
    ull bini = pack2(bs, bs);
    #pragma unroll
    for (int j = 0; j < 8; j++) acc2[j] = bini;
    #pragma unroll 4
    for (int k = 0; k < 512; k++) {
        float w = W[k*128 + tid];
        ull w2 = pack2(w, w);
        const ulonglong2* yr = (const ulonglong2*)&sHT[k][0];
        ulonglong2 y0 = yr[0], y1 = yr[1], y2 = yr[2], y3 = yr[3];
        acc2[0] = fma2(w2, y0.x, acc2[0]); acc2[1] = fma2(w2, y0.y, acc2[1]);
        acc2[2] = fma2(w2, y1.x, acc2[2]); acc2[3] = fma2(w2, y1.y, acc2[3]);
        acc2[4] = fma2(w2, y2.x, acc2[4]); acc2[5] = fma2(w2, y2.y, acc2[5]);
        acc2[6] = fma2(w2, y3.x, acc2[6]); acc2[7] = fma2(w2, y3.y, acc2[7]);
    }
    #pragma unroll
    for (int j = 0; j < 8; j++) {
        float2 u = unpack2(acc2[j]);
        int n = n0 + 2*j;
        if (n < N)     X[((size_t)b*MAXN + n)*C + tid]     += u.x;
        if (n + 1 < N) X[((size_t)b*MAXN + n + 1)*C + tid] += u.y;
    }
}

// ---------------- prune stage 1 ---------------------------------------------
__global__ void k_prune1(float thresh, int pi) {
    int b = blockIdx.x;
    int t = threadIdx.x;
    int tc = g_N - 1;
    __shared__ int ssum[1024];
    __shared__ float sval[1024];
    __shared__ int sidx[1024];
    float am = -1e30f;
    int keep = 0;
    if (t < tc) {
        float s = 0.0f;
        #pragma unroll
        for (int h = 0; h < NH; h++) s += g_CLSP[(b*NH + h)*MAXN + 1 + t];
        am = s * 0.125f;
        keep = (am > thresh) ? 1 : 0;
    }
    ssum[t] = keep; sval[t] = am; sidx[t] = t;
    __syncthreads();
    for (int off = 512; off > 0; off >>= 1) {
        if (t < off) {
            if (sval[t + off] > sval[t] ||
                (sval[t + off] == sval[t] && sidx[t + off] < sidx[t])) {
                sval[t] = sval[t + off]; sidx[t] = sidx[t + off];
            }
        }
        __syncthreads();
    }
    int argidx = sidx[0];
    __syncthreads();
    for (int off = 1; off < 1024; off <<= 1) {
        int v = (t >= off) ? ssum[t - off] : 0;
        __syncthreads();
        ssum[t] += v;
        __syncthreads();
    }
    int total = ssum[1023];
    if (total > 0 && keep) g_order[b][ssum[t] - 1] = t;
    if (t == 0) {
        int cnt = total;
        if (total == 0) { g_order[b][0] = argidx; cnt = 1; }
        g_count[b] = cnt;
        atomicMax(&g_mk[pi], cnt);
    }
}

// ---------------- prune stage 2 ---------------------------------------------
__global__ void k_prune2(const float* __restrict__ Xold, float* __restrict__ Xnew,
                         const float* __restrict__ pos, int pi) {
    int b = blockIdx.y, c = threadIdx.x;
    int mk = g_mk[pi];
    if (blockIdx.x == 0) {
        Xnew[(size_t)b*MAXN*C + c] = Xold[(size_t)b*MAXN*C + c] + pos[c];
        if (b == 0 && c == 0) g_N = 1 + mk;
        return;
    }
    int j = blockIdx.x - 1;
    if (j >= mk) return;
    float v = 0.0f;
    if (j < g_count[b]) {
        int src = g_order[b][j];
        v = Xold[((size_t)b*MAXN + 1 + src)*C + c];
    }
    Xnew[((size_t)b*MAXN + 1 + j)*C + c] = v + pos[(1 + j)*C + c];
}

// ---------------- output copy ----------------------------------------------
__global__ void k_copy(const float* __restrict__ X, float* __restrict__ out,
                       int finalN, int total) {
    int idx = blockIdx.x * 256 + threadIdx.x;
    if (idx >= total) return;
    int per = finalN * C;
    int b = idx / per;
    int rem = idx - b * per;
    out[idx] = X[(size_t)b*MAXN*C + rem];
}

// ---------------- host orchestration ----------------------------------------
extern "C" void kernel_launch(void* const* d_in, const int* in_sizes, int n_in,
                              void* d_out, int out_size) {
    const float* conv_w   = (const float*)d_in[0];
    const float* conv_b   = (const float*)d_in[1];
    const float* cls_tok  = (const float*)d_in[2];
    const float* pos      = (const float*)d_in[3];
    const float* ln1_w    = (const float*)d_in[4];
    const float* ln1_b    = (const float*)d_in[5];
    const float* qkv_w    = (const float*)d_in[6];
    const float* qkv_b    = (const float*)d_in[7];
    const float* out_w    = (const float*)d_in[8];
    const float* out_b    = (const float*)d_in[9];
    const float* ln2_w    = (const float*)d_in[10];
    const float* ln2_b    = (const float*)d_in[11];
    const float* mlp_w1   = (const float*)d_in[12];
    const float* mlp_b1   = (const float*)d_in[13];
    const float* mlp_w2   = (const float*)d_in[14];
    const float* mlp_b2   = (const float*)d_in[15];
    const float* x        = (const float*)d_in[16];
    float* out = (float*)d_out;

    float *pX0, *pX1, *pQ, *pK, *pV, *pO, *pH;
    cudaGetSymbolAddress((void**)&pX0, g_X0);
    cudaGetSymbolAddress((void**)&pX1, g_X1);
    cudaGetSymbolAddress((void**)&pQ,  g_Q);
    cudaGetSymbolAddress((void**)&pK,  g_K);
    cudaGetSymbolAddress((void**)&pV,  g_V);
    cudaGetSymbolAddress((void**)&pO,  g_O);
    cudaGetSymbolAddress((void**)&pH,  g_H);

    const float THRESH[3] = {0.001f, 0.0012f, 0.0015f};

    k_transpose<<<768, 128>>>(conv_w);
    k_patch<<<dim3(65, BATCH), 128>>>(x, conv_b, cls_tok, pos, pX0);

    float* cur = pX0;
    float* alt = pX1;
    dim3 gBlk(65, BATCH);
    dim3 gAtt((MAXN + 127)/128, BATCH*NH);
    dim3 gTok(MAXN, BATCH);

    for (int i = 0; i < L; i++) {
        k_qkvln<<<gBlk, 128>>>(cur, ln1_w + i*C, ln1_b + i*C,
                               qkv_w + (size_t)i*C*384, qkv_b + i*384, pQ, pK, pV);
        k_attn5<<<gAtt, 128>>>(pQ, pK, pV, pO);
        k_proj <<<gBlk, 128>>>(pO, out_w + (size_t)i*C*C, out_b + i*C, cur);
        k_fc1ln<<<gBlk, 128>>>(cur, ln2_w + i*C, ln2_b + i*C,
                               mlp_w1 + (size_t)i*C*512, mlp_b1 + i*512, pH);
        k_fc2  <<<gBlk, 128>>>(pH, mlp_w2 + (size_t)i*512*C, mlp_b2 + i*C, cur);
        if (i < L - 1) {
            k_prune1<<<BATCH, 1024>>>(THRESH[i], i);
            k_prune2<<<gTok, 128>>>(cur, alt, pos, i);
            float* tmp = cur; cur = alt; alt = tmp;
        }
    }

    int finalN = out_size / (BATCH * C);
    int nblk = (out_size + 255) / 256;
    k_copy<<<nblk, 256>>>(cur, out, finalN, out_size);
}